// round 1
// baseline (speedup 1.0000x reference)
#include <cuda_runtime.h>
#include <cuda_bf16.h>
#include <math.h>

#define NN 100000
#define DD 64
#define EE 1000000
#define EPSM 1e-7f

// ---------------- scratch (static __device__, no allocation) ----------------
__device__ float g_denom[(size_t)NN * DD];     // 25.6 MB  sum exp(msg)
__device__ float g_numer[(size_t)NN * DD];     // 25.6 MB  sum msg*exp(msg)
__device__ float g_h[(size_t)NN * 2 * DD];     // 51.2 MB  hidden (pre-BN)
__device__ float g_bnsum[2 * DD];
__device__ float g_bnsumsq[2 * DD];
__device__ float g_bnscale[2 * DD];
__device__ float g_bnshift[2 * DD];

// ---------------- helpers ----------------
__device__ __forceinline__ void red_add_v4(float* p, float a, float b, float c, float d) {
    asm volatile("red.global.add.v4.f32 [%0], {%1,%2,%3,%4};"
                 :: "l"(p), "f"(a), "f"(b), "f"(c), "f"(d) : "memory");
}

// ---------------- kernel 0: zero scratch ----------------
__global__ void zero_kernel() {
    unsigned i = blockIdx.x * blockDim.x + threadIdx.x;   // over float4 of one array
    float4 z = make_float4(0.f, 0.f, 0.f, 0.f);
    if (i < (unsigned)NN * (DD / 4)) {
        reinterpret_cast<float4*>(g_denom)[i] = z;
        reinterpret_cast<float4*>(g_numer)[i] = z;
    }
    if (i < 2 * DD) { g_bnsum[i] = 0.f; g_bnsumsq[i] = 0.f; }
}

// ---------------- kernel 1: edge pass ----------------
// One thread per (edge, 4-feature group): 16 threads per edge.
// Softmax is shift-invariant and msg in [eps, ~5.5], so no segment-max needed.
__global__ void __launch_bounds__(256) edge_kernel(const float4* __restrict__ x4,
                                                   const int* __restrict__ src,
                                                   const int* __restrict__ dst) {
    unsigned idx = blockIdx.x * blockDim.x + threadIdx.x;
    if (idx >= (unsigned)EE * 16u) return;
    unsigned e = idx >> 4, q = idx & 15u;
    int s = __ldg(src + e);
    int t = __ldg(dst + e);
    float4 v = __ldg(x4 + (size_t)s * 16 + q);
    float m0 = fmaxf(v.x, 0.f) + EPSM;
    float m1 = fmaxf(v.y, 0.f) + EPSM;
    float m2 = fmaxf(v.z, 0.f) + EPSM;
    float m3 = fmaxf(v.w, 0.f) + EPSM;
    float e0 = __expf(m0), e1 = __expf(m1), e2 = __expf(m2), e3 = __expf(m3);
    size_t base = (size_t)t * DD + q * 4;
    red_add_v4(g_denom + base, e0, e1, e2, e3);
    red_add_v4(g_numer + base, m0 * e0, m1 * e1, m2 * e2, m3 * e3);
}

// ---------------- kernel 2: agg + residual + Linear1 + BN partial stats ----------------
// Block = 128 threads (one per output column c in [0,128)), 16 nodes per block.
__global__ void __launch_bounds__(128) nodeA_kernel(const float* __restrict__ x,
                                                    const float* __restrict__ W1,
                                                    const float* __restrict__ b1) {
    __shared__ float s_out[16][DD];
    int c = threadIdx.x;
    int n0 = blockIdx.x * 16;

    // stage: out = numer/(denom+1e-16) + x   (16*64 = 1024 elems, 8 per thread)
    for (int i = c; i < 16 * DD; i += 128) {
        int n = i >> 6, d = i & 63;
        size_t g = (size_t)(n0 + n) * DD + d;
        float den = g_denom[g];
        float agg = g_numer[g] / (den + 1e-16f);
        s_out[n][d] = agg + __ldg(x + g);
    }

    // W1 column c into registers (coalesced across threads)
    float w1c[DD];
#pragma unroll
    for (int k = 0; k < DD; k++) w1c[k] = __ldg(&W1[k * 128 + c]);
    float bc = __ldg(&b1[c]);
    __syncthreads();

    float sum = 0.f, sq = 0.f;
#pragma unroll 1
    for (int n = 0; n < 16; n++) {
        float acc = bc;
#pragma unroll
        for (int k = 0; k < DD; k++) acc = fmaf(s_out[n][k], w1c[k], acc);
        g_h[(size_t)(n0 + n) * 128 + c] = acc;
        sum += acc;
        sq = fmaf(acc, acc, sq);
    }
    atomicAdd(&g_bnsum[c], sum);
    atomicAdd(&g_bnsumsq[c], sq);
}

// ---------------- kernel 3: BN finalize (1 block, 128 threads) ----------------
__global__ void bnfin_kernel(const float* __restrict__ gam, const float* __restrict__ bet) {
    int c = threadIdx.x;
    float mean = g_bnsum[c] * (1.f / (float)NN);
    float var  = g_bnsumsq[c] * (1.f / (float)NN) - mean * mean;
    float sc = __ldg(gam + c) * rsqrtf(var + 1e-5f);
    g_bnscale[c] = sc;
    g_bnshift[c] = __ldg(bet + c) - mean * sc;
}

// ---------------- kernel 4: BN + ReLU + Linear2 + LayerNorm + ReLU ----------------
// Block = 128 threads, 16 nodes per block.
__global__ void __launch_bounds__(128) nodeB_kernel(const float* __restrict__ W2,
                                                    const float* __restrict__ b2,
                                                    const float* __restrict__ lng,
                                                    const float* __restrict__ lnb,
                                                    float* __restrict__ out) {
    __shared__ float s_W2[128 * DD];  // 32 KB
    __shared__ float s_a[16][128];    // 8 KB
    __shared__ float s_y[16][DD];     // 4 KB
    int t = threadIdx.x;
    int n0 = blockIdx.x * 16;

    for (int i = t; i < 128 * DD; i += 128) s_W2[i] = __ldg(W2 + i);
    for (int i = t; i < 16 * 128; i += 128) {
        int n = i >> 7, k = i & 127;
        float v = g_h[(size_t)(n0 + n) * 128 + k];
        v = fmaf(v, g_bnscale[k], g_bnshift[k]);
        s_a[n][k] = fmaxf(v, 0.f);
    }
    __syncthreads();

    int c = t & 63, half = t >> 6;
    float bc = __ldg(&b2[c]);
    for (int n = half; n < 16; n += 2) {
        float acc = bc;
#pragma unroll
        for (int k = 0; k < 128; k++) acc = fmaf(s_a[n][k], s_W2[k * DD + c], acc);
        s_y[n][c] = acc;
    }
    __syncthreads();

    // LayerNorm + ReLU: warp w handles nodes 4w..4w+3 (64 vals = 2 per lane)
    int w = t >> 5, lane = t & 31;
#pragma unroll
    for (int nn = 0; nn < 4; nn++) {
        int n = w * 4 + nn;
        float v0 = s_y[n][lane];
        float v1 = s_y[n][lane + 32];
        float sum = v0 + v1;
        float sq  = v0 * v0 + v1 * v1;
#pragma unroll
        for (int o = 16; o > 0; o >>= 1) {
            sum += __shfl_xor_sync(0xFFFFFFFFu, sum, o);
            sq  += __shfl_xor_sync(0xFFFFFFFFu, sq, o);
        }
        float mean = sum * (1.f / 64.f);
        float var  = sq * (1.f / 64.f) - mean * mean;
        float inv  = rsqrtf(var + 1e-5f);
        size_t g = (size_t)(n0 + n) * DD;
        float y0 = (v0 - mean) * inv * __ldg(lng + lane)      + __ldg(lnb + lane);
        float y1 = (v1 - mean) * inv * __ldg(lng + lane + 32) + __ldg(lnb + lane + 32);
        out[g + lane]      = fmaxf(y0, 0.f);
        out[g + lane + 32] = fmaxf(y1, 0.f);
    }
}

// ---------------- launcher ----------------
extern "C" void kernel_launch(void* const* d_in, const int* in_sizes, int n_in,
                              void* d_out, int out_size) {
    const float* x   = (const float*)d_in[0];
    const int*   ei  = (const int*)d_in[1];
    const float* W1  = (const float*)d_in[2];
    const float* b1  = (const float*)d_in[3];
    const float* bng = (const float*)d_in[4];
    const float* bnb = (const float*)d_in[5];
    const float* W2  = (const float*)d_in[6];
    const float* b2  = (const float*)d_in[7];
    const float* lng = (const float*)d_in[8];
    const float* lnb = (const float*)d_in[9];
    float* out = (float*)d_out;

    const int* src = ei;        // edge_index[0]
    const int* dst = ei + EE;   // edge_index[1]

    {
        unsigned n = (unsigned)NN * (DD / 4);  // 1.6M float4 per array
        zero_kernel<<<(n + 255) / 256, 256>>>();
    }
    {
        unsigned n = (unsigned)EE * 16u;       // 16M threads
        edge_kernel<<<(n + 255) / 256, 256>>>((const float4*)x, src, dst);
    }
    nodeA_kernel<<<NN / 16, 128>>>(x, W1, b1);
    bnfin_kernel<<<1, 128>>>(bng, bnb);
    nodeB_kernel<<<NN / 16, 128>>>(W2, b2, lng, lnb, out);
}